// round 13
// baseline (speedup 1.0000x reference)
#include <cuda_runtime.h>
#include <cuda_fp16.h>

#define N_NODES 100000
#define N_EDGES 1600000
#define NB_SCAN ((N_NODES + 1023) / 1024)   // 98 scan blocks

// ---------------- scratch (static device globals; no allocation allowed) ----
// g_cnt invariant: zero at entry of every kernel_launch execution (initially
// zero-initialized; scan_kernel re-zeroes it after consuming it).
// g_total: reset by deg_kernel (runs strictly before scan_kernel each launch).
__device__ __align__(16) int      g_cnt [N_NODES];
__device__ __align__(16) int      g_off [N_NODES];
__device__ __align__(16) int      g_cur [N_NODES];
__device__            int         g_total;
__device__ __align__(16) float    g_dinv[N_NODES];
__device__ __align__(16) unsigned g_csr [N_EDGES];      // (src<<15)|fp16(dinv[src])
__device__ __align__(16) __half   g_h1  [N_NODES * 64]; // layer-1 transformed feats
__device__ __align__(16) __half   g_h2  [N_NODES * 64]; // layer-2 transformed feats
__device__ __align__(16) __half   g_h3  [N_NODES * 32]; // layer-3 transformed feats

// pack/unpack: src in [0,2^17), dinv in (0,1] so fp16 sign bit is 0 -> 15 bits
__device__ __forceinline__ unsigned pack_edge(int s, float dv_s) {
    unsigned h = (unsigned)__half_as_ushort(__float2half_rn(dv_s));  // bit15==0
    return ((unsigned)s << 15) | h;
}
__device__ __forceinline__ int unpack_src(unsigned u) { return (int)(u >> 15); }
__device__ __forceinline__ float unpack_dinv(unsigned u) {
    return __half2float(__ushort_as_half((unsigned short)(u & 0x7FFFu)));
}

// ---------------- CSR construction ------------------------------------------
// 8 edges per thread (two int4 loads); also resets g_total for this launch.
__global__ void deg_kernel(const int* __restrict__ dst) {
    if (blockIdx.x == 0 && threadIdx.x == 0) g_total = 0;
    int base = (blockIdx.x * blockDim.x + threadIdx.x) * 8;
    if (base >= N_EDGES) return;
    int4 d4a = *(const int4*)(dst + base);
    int4 d4b = *(const int4*)(dst + base + 4);
    atomicAdd(&g_cnt[d4a.x], 1);
    atomicAdd(&g_cnt[d4a.y], 1);
    atomicAdd(&g_cnt[d4a.z], 1);
    atomicAdd(&g_cnt[d4a.w], 1);
    atomicAdd(&g_cnt[d4b.x], 1);
    atomicAdd(&g_cnt[d4b.y], 1);
    atomicAdd(&g_cnt[d4b.z], 1);
    atomicAdd(&g_cnt[d4b.w], 1);
}

// single-pass CSR offsets: per-block exclusive scan + ONE atomic block-base.
// Rows need not be in node order — any disjoint contiguous allocation works,
// since aggs only read [off, off+cnt). Also computes dinv, inits cursors,
// re-zeroes g_cnt (replay invariant).
__global__ void scan_kernel() {
    __shared__ int sh[1024];
    __shared__ int base_sh;
    int i = blockIdx.x * 1024 + threadIdx.x;
    int v = (i < N_NODES) ? g_cnt[i] : 0;
    if (i < N_NODES) g_dinv[i] = rsqrtf((float)v + 1.0f);  // +1 self-loop
    sh[threadIdx.x] = v;
    __syncthreads();
#pragma unroll
    for (int s = 1; s < 1024; s <<= 1) {
        int t = 0;
        if (threadIdx.x >= s) t = sh[threadIdx.x - s];
        __syncthreads();
        if (threadIdx.x >= s) sh[threadIdx.x] += t;
        __syncthreads();
    }
    if (threadIdx.x == 1023) base_sh = atomicAdd(&g_total, sh[1023]);
    __syncthreads();
    if (i < N_NODES) {
        int o = base_sh + sh[threadIdx.x] - v;   // block base + local exclusive
        g_off[i] = o;
        g_cur[i] = o;
        g_cnt[i] = 0;   // restore invariant for next replay
    }
}

// scatter edges into CSR order; 8 edges/thread; packs fp16(dinv[src]) only
// (dinv[dst] is applied in the agg, where it's already a register)
__global__ void scatter_kernel(const int* __restrict__ src,
                               const int* __restrict__ dst) {
    int base = (blockIdx.x * blockDim.x + threadIdx.x) * 8;
    if (base >= N_EDGES) return;
    int4 s4a = *(const int4*)(src + base);
    int4 s4b = *(const int4*)(src + base + 4);
    int4 d4a = *(const int4*)(dst + base);
    int4 d4b = *(const int4*)(dst + base + 4);
    float a0 = g_dinv[s4a.x], a1 = g_dinv[s4a.y], a2 = g_dinv[s4a.z], a3 = g_dinv[s4a.w];
    float a4 = g_dinv[s4b.x], a5 = g_dinv[s4b.y], a6 = g_dinv[s4b.z], a7 = g_dinv[s4b.w];
    int p0 = atomicAdd(&g_cur[d4a.x], 1);
    int p1 = atomicAdd(&g_cur[d4a.y], 1);
    int p2 = atomicAdd(&g_cur[d4a.z], 1);
    int p3 = atomicAdd(&g_cur[d4a.w], 1);
    int p4 = atomicAdd(&g_cur[d4b.x], 1);
    int p5 = atomicAdd(&g_cur[d4b.y], 1);
    int p6 = atomicAdd(&g_cur[d4b.z], 1);
    int p7 = atomicAdd(&g_cur[d4b.w], 1);
    g_csr[p0] = pack_edge(s4a.x, a0);
    g_csr[p1] = pack_edge(s4a.y, a1);
    g_csr[p2] = pack_edge(s4a.z, a2);
    g_csr[p3] = pack_edge(s4a.w, a3);
    g_csr[p4] = pack_edge(s4b.x, a4);
    g_csr[p5] = pack_edge(s4b.y, a5);
    g_csr[p6] = pack_edge(s4b.z, a6);
    g_csr[p7] = pack_edge(s4b.w, a7);
}

// ---------------- tensor-core GEMM: H[n,FOUT](fp16) = X[n,64](fp32) @ W -----
template <int FOUT>
__global__ void __launch_bounds__(128) gemm_mma_kernel(const float* __restrict__ X,
                                                       const float* __restrict__ W,
                                                       __half* __restrict__ H, int n) {
    constexpr int LDA = 72;
    constexpr int NT  = FOUT / 8;
    __shared__ __half As[64 * LDA];
    __shared__ __half Bs[64 * LDA];
    int tid  = threadIdx.x;
    int row0 = blockIdx.x * 64;

    for (int p = tid; p < 64 * 32; p += 128) {
        int r  = p >> 5;
        int cp = p & 31;
        int gr = row0 + r;
        float2 v = (gr < n) ? ((const float2*)(X + (size_t)gr * 64))[cp]
                            : make_float2(0.f, 0.f);
        *(__half2*)&As[r * LDA + 2 * cp] = __floats2half2_rn(v.x, v.y);
    }
    for (int p = tid; p < 64 * (FOUT / 2); p += 128) {
        int r  = p / (FOUT / 2);
        int cp = p % (FOUT / 2);
        float2 v = ((const float2*)(W + (size_t)r * FOUT))[cp];
        *(__half2*)&Bs[r * LDA + 2 * cp] = __floats2half2_rn(v.x, v.y);
    }
    __syncthreads();

    int warp = tid >> 5;
    int lane = tid & 31;
    float acc[NT][4];
#pragma unroll
    for (int t = 0; t < NT; t++) {
        acc[t][0] = 0.f; acc[t][1] = 0.f; acc[t][2] = 0.f; acc[t][3] = 0.f;
    }
#pragma unroll
    for (int kk = 0; kk < 4; kk++) {
        unsigned a0, a1, a2, a3;
        {
            int arow = warp * 16 + (lane & 15);
            int acol = kk * 16 + (lane >> 4) * 8;
            unsigned aaddr = (unsigned)__cvta_generic_to_shared(&As[arow * LDA + acol]);
            asm volatile("ldmatrix.sync.aligned.m8n8.x4.shared.b16 {%0,%1,%2,%3}, [%4];"
                         : "=r"(a0), "=r"(a1), "=r"(a2), "=r"(a3) : "r"(aaddr));
        }
#pragma unroll
        for (int nt = 0; nt < NT; nt++) {
            unsigned b0, b1;
            int brow = kk * 16 + (lane & 15);
            unsigned baddr = (unsigned)__cvta_generic_to_shared(&Bs[brow * LDA + nt * 8]);
            asm volatile("ldmatrix.sync.aligned.m8n8.x2.trans.shared.b16 {%0,%1}, [%2];"
                         : "=r"(b0), "=r"(b1) : "r"(baddr));
            asm volatile("mma.sync.aligned.m16n8k16.row.col.f32.f16.f16.f32 "
                         "{%0,%1,%2,%3}, {%4,%5,%6,%7}, {%8,%9}, {%0,%1,%2,%3};"
                         : "+f"(acc[nt][0]), "+f"(acc[nt][1]),
                           "+f"(acc[nt][2]), "+f"(acc[nt][3])
                         : "r"(a0), "r"(a1), "r"(a2), "r"(a3), "r"(b0), "r"(b1));
        }
    }
    int r0    = row0 + warp * 16 + (lane >> 2);
    int cbase = (lane & 3) * 2;
#pragma unroll
    for (int nt = 0; nt < NT; nt++) {
        if (r0 < n)
            *(__half2*)&H[(size_t)r0 * FOUT + nt * 8 + cbase] =
                __floats2half2_rn(acc[nt][0], acc[nt][1]);
        if (r0 + 8 < n)
            *(__half2*)&H[(size_t)(r0 + 8) * FOUT + nt * 8 + cbase] =
                __floats2half2_rn(acc[nt][2], acc[nt][3]);
    }
}

// ---------------- fused agg(layer l) + GEMM(layer l+1) ----------------------
// 256 threads: 8 warps x 8 nodes in agg phase; warps 0-3 mma.
// norm = unpack_dinv(e) * dinv[node] (register).
template <int FOUT>
__global__ void __launch_bounds__(256) fused_kernel(const __half* __restrict__ h_in,
                                                    const float* __restrict__ bias,
                                                    const float* __restrict__ W,
                                                    __half* __restrict__ H, int n) {
    constexpr int LDA = 72;
    constexpr int NT  = FOUT / 8;
    __shared__ __half As[64 * LDA];
    __shared__ __half Bs[64 * LDA];
    int tid   = threadIdx.x;
    int warp  = tid >> 5;
    int lane  = tid & 31;
    int node0 = blockIdx.x * 64;

    // stage W (64 x FOUT) fp32 -> fp16
    for (int p = tid; p < 64 * (FOUT / 2); p += 256) {
        int r  = p / (FOUT / 2);
        int cp = p % (FOUT / 2);
        float2 v = ((const float2*)(W + (size_t)r * FOUT))[cp];
        *(__half2*)&Bs[r * LDA + 2 * cp] = __floats2half2_rn(v.x, v.y);
    }

    // agg phase: warp w handles local rows w*8 .. w*8+7
    const half2* hb = (const half2*)h_in;
    float2 bb = ((const float2*)bias)[lane];
    for (int k = 0; k < 8; k++) {
        int lr   = warp * 8 + k;
        int node = node0 + lr;
        if (node >= n) break;
        float dv  = g_dinv[node];
        float s2  = dv * dv;
        int   beg = g_off[node];
        int   end = g_cur[node];
        float2 self = __half22float2(hb[(size_t)node * 32 + lane]);
        float2 acc;
        acc.x = self.x * s2;
        acc.y = self.y * s2;
        int i = beg;
        for (; i + 8 <= end; i += 8) {
            unsigned e[8];
#pragma unroll
            for (int j = 0; j < 8; j++) e[j] = g_csr[i + j];
            float2 v[8];
#pragma unroll
            for (int j = 0; j < 8; j++)
                v[j] = __half22float2(hb[(size_t)unpack_src(e[j]) * 32 + lane]);
#pragma unroll
            for (int j = 0; j < 8; j++) {
                float nm = unpack_dinv(e[j]) * dv;
                acc.x = fmaf(nm, v[j].x, acc.x);
                acc.y = fmaf(nm, v[j].y, acc.y);
            }
        }
        for (; i < end; i++) {
            unsigned e0 = g_csr[i];
            float2 v0 = __half22float2(hb[(size_t)unpack_src(e0) * 32 + lane]);
            float nm = unpack_dinv(e0) * dv;
            acc.x = fmaf(nm, v0.x, acc.x);
            acc.y = fmaf(nm, v0.y, acc.y);
        }
        acc.x = fmaxf(acc.x + bb.x, 0.f);   // bias + relu (layers 1,2 both relu)
        acc.y = fmaxf(acc.y + bb.y, 0.f);
        *(__half2*)&As[lr * LDA + 2 * lane] = __floats2half2_rn(acc.x, acc.y);
    }
    __syncthreads();

    // mma phase: warps 0-3 compute the 64 x FOUT tile
    if (warp < 4) {
        float acc[NT][4];
#pragma unroll
        for (int t = 0; t < NT; t++) {
            acc[t][0] = 0.f; acc[t][1] = 0.f; acc[t][2] = 0.f; acc[t][3] = 0.f;
        }
#pragma unroll
        for (int kk = 0; kk < 4; kk++) {
            unsigned a0, a1, a2, a3;
            {
                int arow = warp * 16 + (lane & 15);
                int acol = kk * 16 + (lane >> 4) * 8;
                unsigned aaddr = (unsigned)__cvta_generic_to_shared(&As[arow * LDA + acol]);
                asm volatile("ldmatrix.sync.aligned.m8n8.x4.shared.b16 {%0,%1,%2,%3}, [%4];"
                             : "=r"(a0), "=r"(a1), "=r"(a2), "=r"(a3) : "r"(aaddr));
            }
#pragma unroll
            for (int nt = 0; nt < NT; nt++) {
                unsigned b0, b1;
                int brow = kk * 16 + (lane & 15);
                unsigned baddr = (unsigned)__cvta_generic_to_shared(&Bs[brow * LDA + nt * 8]);
                asm volatile("ldmatrix.sync.aligned.m8n8.x2.trans.shared.b16 {%0,%1}, [%2];"
                             : "=r"(b0), "=r"(b1) : "r"(baddr));
                asm volatile("mma.sync.aligned.m16n8k16.row.col.f32.f16.f16.f32 "
                             "{%0,%1,%2,%3}, {%4,%5,%6,%7}, {%8,%9}, {%0,%1,%2,%3};"
                             : "+f"(acc[nt][0]), "+f"(acc[nt][1]),
                               "+f"(acc[nt][2]), "+f"(acc[nt][3])
                             : "r"(a0), "r"(a1), "r"(a2), "r"(a3), "r"(b0), "r"(b1));
            }
        }
        int r0    = node0 + warp * 16 + (lane >> 2);
        int cbase = (lane & 3) * 2;
#pragma unroll
        for (int nt = 0; nt < NT; nt++) {
            if (r0 < n)
                *(__half2*)&H[(size_t)r0 * FOUT + nt * 8 + cbase] =
                    __floats2half2_rn(acc[nt][0], acc[nt][1]);
            if (r0 + 8 < n)
                *(__half2*)&H[(size_t)(r0 + 8) * FOUT + nt * 8 + cbase] =
                    __floats2half2_rn(acc[nt][2], acc[nt][3]);
        }
    }
}

// ---------------- final aggregation (layer 3, F=32, no relu, fp32 out) ------
__global__ void __launch_bounds__(256) agg_final_kernel(const __half* __restrict__ h,
                                                        const float* __restrict__ bias,
                                                        float* __restrict__ out) {
    int node = (blockIdx.x * 256 + threadIdx.x) >> 5;
    int lane = threadIdx.x & 31;
    if (node >= N_NODES) return;

    float dv  = g_dinv[node];
    float s2  = dv * dv;
    int   beg = g_off[node];
    int   end = g_cur[node];

    float acc = __half2float(h[(size_t)node * 32 + lane]) * s2;
    int i = beg;
    for (; i + 8 <= end; i += 8) {
        unsigned e[8];
#pragma unroll
        for (int j = 0; j < 8; j++) e[j] = g_csr[i + j];
        float v[8];
#pragma unroll
        for (int j = 0; j < 8; j++)
            v[j] = __half2float(h[(size_t)unpack_src(e[j]) * 32 + lane]);
#pragma unroll
        for (int j = 0; j < 8; j++)
            acc = fmaf(unpack_dinv(e[j]) * dv, v[j], acc);
    }
    for (; i < end; i++) {
        unsigned e0 = g_csr[i];
        acc = fmaf(unpack_dinv(e0) * dv,
                   __half2float(h[(size_t)unpack_src(e0) * 32 + lane]), acc);
    }
    acc += bias[lane];
    out[(size_t)node * 32 + lane] = acc;
}

// ---------------- host-side launcher ---------------------------------------
extern "C" void kernel_launch(void* const* d_in, const int* in_sizes, int n_in,
                              void* d_out, int out_size) {
    const float* x   = (const float*)d_in[0];
    const int*   ei  = (const int*)d_in[1];     // int32 (JAX x64 disabled)
    const int*   src = ei;
    const int*   dst = ei + N_EDGES;
    const float* W1  = (const float*)d_in[2];
    const float* b1  = (const float*)d_in[3];
    const float* W2  = (const float*)d_in[4];
    const float* b2  = (const float*)d_in[5];
    const float* W3  = (const float*)d_in[6];
    const float* b3  = (const float*)d_in[7];
    float* out = (float*)d_out;

    void *p_h1, *p_h2, *p_h3;
    cudaGetSymbolAddress(&p_h1, g_h1);
    cudaGetSymbolAddress(&p_h2, g_h2);
    cudaGetSymbolAddress(&p_h3, g_h3);
    __half* h1 = (__half*)p_h1;
    __half* h2 = (__half*)p_h2;
    __half* h3 = (__half*)p_h3;

    const int n  = N_NODES;
    const int TB = 256;
    const int gE8 = (N_EDGES / 8 + TB - 1) / TB;
    const int gT  = (N_NODES + 63) / 64;
    const int gAgg = (N_NODES * 32 + TB - 1) / TB;

    // --- CSR build (3 launches) ---
    deg_kernel<<<gE8, TB>>>(dst);
    scan_kernel<<<NB_SCAN, 1024>>>();
    scatter_kernel<<<gE8, TB>>>(src, dst);

    // --- layers ---
    gemm_mma_kernel<64><<<gT, 128>>>(x, W1, h1, n);          // h1 = X @ W1
    fused_kernel<64><<<gT, TB>>>(h1, b1, W2, h2, n);         // h2 = relu(agg h1 + b1) @ W2
    fused_kernel<32><<<gT, TB>>>(h2, b2, W3, h3, n);         // h3 = relu(agg h2 + b2) @ W3
    agg_final_kernel<<<gAgg, TB>>>(h3, b3, out);             // out = agg h3 + b3
}

// round 14
// speedup vs baseline: 1.0562x; 1.0562x over previous
#include <cuda_runtime.h>
#include <cuda_fp16.h>

#define N_NODES 100000
#define N_EDGES 1600000
#define NB_SCAN ((N_NODES + 1023) / 1024)   // 98 scan blocks

// ---------------- scratch (static device globals; no allocation allowed) ----
// g_cnt invariant: zero at entry of every kernel_launch execution (initially
// zero-initialized; scan_kernel re-zeroes it after consuming it).
// g_total: reset by deg_kernel (runs strictly before scan_kernel each launch).
__device__ __align__(16) int      g_cnt [N_NODES];
__device__ __align__(16) int      g_off [N_NODES];
__device__ __align__(16) int      g_cur [N_NODES];
__device__            int         g_total;
__device__ __align__(16) float    g_dinv[N_NODES];
__device__ __align__(16) unsigned g_csr [N_EDGES];      // (src<<15)|fp16(dinv[src])
__device__ __align__(16) __half   g_h1  [N_NODES * 64]; // layer-1 transformed feats
__device__ __align__(16) __half   g_h2  [N_NODES * 64]; // layer-2 transformed feats
__device__ __align__(16) __half   g_h3  [N_NODES * 32]; // layer-3 transformed feats

// pack/unpack: src in [0,2^17), dinv in (0,1] so fp16 sign bit is 0 -> 15 bits
__device__ __forceinline__ unsigned pack_edge(int s, float dv_s) {
    unsigned h = (unsigned)__half_as_ushort(__float2half_rn(dv_s));  // bit15==0
    return ((unsigned)s << 15) | h;
}
__device__ __forceinline__ int unpack_src(unsigned u) { return (int)(u >> 15); }
__device__ __forceinline__ float unpack_dinv(unsigned u) {
    return __half2float(__ushort_as_half((unsigned short)(u & 0x7FFFu)));
}

// ---------------- CSR construction ------------------------------------------
// 8 edges per thread (two int4 loads); also resets g_total for this launch.
__global__ void deg_kernel(const int* __restrict__ dst) {
    if (blockIdx.x == 0 && threadIdx.x == 0) g_total = 0;
    int base = (blockIdx.x * blockDim.x + threadIdx.x) * 8;
    if (base >= N_EDGES) return;
    int4 d4a = *(const int4*)(dst + base);
    int4 d4b = *(const int4*)(dst + base + 4);
    atomicAdd(&g_cnt[d4a.x], 1);
    atomicAdd(&g_cnt[d4a.y], 1);
    atomicAdd(&g_cnt[d4a.z], 1);
    atomicAdd(&g_cnt[d4a.w], 1);
    atomicAdd(&g_cnt[d4b.x], 1);
    atomicAdd(&g_cnt[d4b.y], 1);
    atomicAdd(&g_cnt[d4b.z], 1);
    atomicAdd(&g_cnt[d4b.w], 1);
}

// single-pass CSR offsets: per-block exclusive scan + ONE atomic block-base.
// Rows need not be in node order — any disjoint contiguous allocation works.
// Also computes dinv, inits cursors, re-zeroes g_cnt (replay invariant).
__global__ void scan_kernel() {
    __shared__ int sh[1024];
    __shared__ int base_sh;
    int i = blockIdx.x * 1024 + threadIdx.x;
    int v = (i < N_NODES) ? g_cnt[i] : 0;
    if (i < N_NODES) g_dinv[i] = rsqrtf((float)v + 1.0f);  // +1 self-loop
    sh[threadIdx.x] = v;
    __syncthreads();
#pragma unroll
    for (int s = 1; s < 1024; s <<= 1) {
        int t = 0;
        if (threadIdx.x >= s) t = sh[threadIdx.x - s];
        __syncthreads();
        if (threadIdx.x >= s) sh[threadIdx.x] += t;
        __syncthreads();
    }
    if (threadIdx.x == 1023) base_sh = atomicAdd(&g_total, sh[1023]);
    __syncthreads();
    if (i < N_NODES) {
        int o = base_sh + sh[threadIdx.x] - v;   // block base + local exclusive
        g_off[i] = o;
        g_cur[i] = o;
        g_cnt[i] = 0;   // restore invariant for next replay
    }
}

// scatter edges into CSR order; 8 edges/thread; packs fp16(dinv[src]) only
__global__ void scatter_kernel(const int* __restrict__ src,
                               const int* __restrict__ dst) {
    int base = (blockIdx.x * blockDim.x + threadIdx.x) * 8;
    if (base >= N_EDGES) return;
    int4 s4a = *(const int4*)(src + base);
    int4 s4b = *(const int4*)(src + base + 4);
    int4 d4a = *(const int4*)(dst + base);
    int4 d4b = *(const int4*)(dst + base + 4);
    float a0 = g_dinv[s4a.x], a1 = g_dinv[s4a.y], a2 = g_dinv[s4a.z], a3 = g_dinv[s4a.w];
    float a4 = g_dinv[s4b.x], a5 = g_dinv[s4b.y], a6 = g_dinv[s4b.z], a7 = g_dinv[s4b.w];
    int p0 = atomicAdd(&g_cur[d4a.x], 1);
    int p1 = atomicAdd(&g_cur[d4a.y], 1);
    int p2 = atomicAdd(&g_cur[d4a.z], 1);
    int p3 = atomicAdd(&g_cur[d4a.w], 1);
    int p4 = atomicAdd(&g_cur[d4b.x], 1);
    int p5 = atomicAdd(&g_cur[d4b.y], 1);
    int p6 = atomicAdd(&g_cur[d4b.z], 1);
    int p7 = atomicAdd(&g_cur[d4b.w], 1);
    g_csr[p0] = pack_edge(s4a.x, a0);
    g_csr[p1] = pack_edge(s4a.y, a1);
    g_csr[p2] = pack_edge(s4a.z, a2);
    g_csr[p3] = pack_edge(s4a.w, a3);
    g_csr[p4] = pack_edge(s4b.x, a4);
    g_csr[p5] = pack_edge(s4b.y, a5);
    g_csr[p6] = pack_edge(s4b.z, a6);
    g_csr[p7] = pack_edge(s4b.w, a7);
}

// ---------------- tensor-core GEMM: H[n,FOUT](fp16) = X[n,64](fp32) @ W -----
// 128-row tile, 256 threads, float4 staging: high DRAM MLP for the X stream.
template <int FOUT>
__global__ void __launch_bounds__(256) gemm_mma_kernel(const float* __restrict__ X,
                                                       const float* __restrict__ W,
                                                       __half* __restrict__ H, int n) {
    constexpr int LDA = 72;
    constexpr int NT  = FOUT / 8;
    __shared__ __half As[128 * LDA];
    __shared__ __half Bs[64 * LDA];
    int tid  = threadIdx.x;
    int row0 = blockIdx.x * 128;

    // stage A tile (128 x 64) fp32 -> fp16, float4 loads (2 per thread)
#pragma unroll
    for (int p = tid; p < 128 * 16; p += 256) {
        int r  = p >> 4;
        int c4 = p & 15;
        int gr = row0 + r;
        float4 v = (gr < n) ? ((const float4*)(X + (size_t)gr * 64))[c4]
                            : make_float4(0.f, 0.f, 0.f, 0.f);
        *(__half2*)&As[r * LDA + c4 * 4]     = __floats2half2_rn(v.x, v.y);
        *(__half2*)&As[r * LDA + c4 * 4 + 2] = __floats2half2_rn(v.z, v.w);
    }
    // stage W (64 x FOUT) fp32 -> fp16, float4 loads
    for (int p = tid; p < 64 * (FOUT / 4); p += 256) {
        int r  = p / (FOUT / 4);
        int c4 = p % (FOUT / 4);
        float4 v = ((const float4*)(W + (size_t)r * FOUT))[c4];
        *(__half2*)&Bs[r * LDA + c4 * 4]     = __floats2half2_rn(v.x, v.y);
        *(__half2*)&Bs[r * LDA + c4 * 4 + 2] = __floats2half2_rn(v.z, v.w);
    }
    __syncthreads();

    int warp = tid >> 5;   // 8 warps, 16 rows each
    int lane = tid & 31;
    float acc[NT][4];
#pragma unroll
    for (int t = 0; t < NT; t++) {
        acc[t][0] = 0.f; acc[t][1] = 0.f; acc[t][2] = 0.f; acc[t][3] = 0.f;
    }
#pragma unroll
    for (int kk = 0; kk < 4; kk++) {
        unsigned a0, a1, a2, a3;
        {
            int arow = warp * 16 + (lane & 15);
            int acol = kk * 16 + (lane >> 4) * 8;
            unsigned aaddr = (unsigned)__cvta_generic_to_shared(&As[arow * LDA + acol]);
            asm volatile("ldmatrix.sync.aligned.m8n8.x4.shared.b16 {%0,%1,%2,%3}, [%4];"
                         : "=r"(a0), "=r"(a1), "=r"(a2), "=r"(a3) : "r"(aaddr));
        }
#pragma unroll
        for (int nt = 0; nt < NT; nt++) {
            unsigned b0, b1;
            int brow = kk * 16 + (lane & 15);
            unsigned baddr = (unsigned)__cvta_generic_to_shared(&Bs[brow * LDA + nt * 8]);
            asm volatile("ldmatrix.sync.aligned.m8n8.x2.trans.shared.b16 {%0,%1}, [%2];"
                         : "=r"(b0), "=r"(b1) : "r"(baddr));
            asm volatile("mma.sync.aligned.m16n8k16.row.col.f32.f16.f16.f32 "
                         "{%0,%1,%2,%3}, {%4,%5,%6,%7}, {%8,%9}, {%0,%1,%2,%3};"
                         : "+f"(acc[nt][0]), "+f"(acc[nt][1]),
                           "+f"(acc[nt][2]), "+f"(acc[nt][3])
                         : "r"(a0), "r"(a1), "r"(a2), "r"(a3), "r"(b0), "r"(b1));
        }
    }
    int r0    = row0 + warp * 16 + (lane >> 2);
    int cbase = (lane & 3) * 2;
#pragma unroll
    for (int nt = 0; nt < NT; nt++) {
        if (r0 < n)
            *(__half2*)&H[(size_t)r0 * FOUT + nt * 8 + cbase] =
                __floats2half2_rn(acc[nt][0], acc[nt][1]);
        if (r0 + 8 < n)
            *(__half2*)&H[(size_t)(r0 + 8) * FOUT + nt * 8 + cbase] =
                __floats2half2_rn(acc[nt][2], acc[nt][3]);
    }
}

// ---------------- fused agg(layer l) + GEMM(layer l+1) ----------------------
// 256 threads: 8 warps x 8 nodes in agg phase; warps 0-3 mma.
template <int FOUT>
__global__ void __launch_bounds__(256) fused_kernel(const __half* __restrict__ h_in,
                                                    const float* __restrict__ bias,
                                                    const float* __restrict__ W,
                                                    __half* __restrict__ H, int n) {
    constexpr int LDA = 72;
    constexpr int NT  = FOUT / 8;
    __shared__ __half As[64 * LDA];
    __shared__ __half Bs[64 * LDA];
    int tid   = threadIdx.x;
    int warp  = tid >> 5;
    int lane  = tid & 31;
    int node0 = blockIdx.x * 64;

    // stage W (64 x FOUT) fp32 -> fp16
    for (int p = tid; p < 64 * (FOUT / 2); p += 256) {
        int r  = p / (FOUT / 2);
        int cp = p % (FOUT / 2);
        float2 v = ((const float2*)(W + (size_t)r * FOUT))[cp];
        *(__half2*)&Bs[r * LDA + 2 * cp] = __floats2half2_rn(v.x, v.y);
    }

    // agg phase: warp w handles local rows w*8 .. w*8+7
    const half2* hb = (const half2*)h_in;
    float2 bb = ((const float2*)bias)[lane];
    for (int k = 0; k < 8; k++) {
        int lr   = warp * 8 + k;
        int node = node0 + lr;
        if (node >= n) break;
        float dv  = g_dinv[node];
        float s2  = dv * dv;
        int   beg = g_off[node];
        int   end = g_cur[node];
        float2 self = __half22float2(hb[(size_t)node * 32 + lane]);
        float2 acc;
        acc.x = self.x * s2;
        acc.y = self.y * s2;
        int i = beg;
        for (; i + 8 <= end; i += 8) {
            unsigned e[8];
#pragma unroll
            for (int j = 0; j < 8; j++) e[j] = g_csr[i + j];
            float2 v[8];
#pragma unroll
            for (int j = 0; j < 8; j++)
                v[j] = __half22float2(hb[(size_t)unpack_src(e[j]) * 32 + lane]);
#pragma unroll
            for (int j = 0; j < 8; j++) {
                float nm = unpack_dinv(e[j]) * dv;
                acc.x = fmaf(nm, v[j].x, acc.x);
                acc.y = fmaf(nm, v[j].y, acc.y);
            }
        }
        for (; i < end; i++) {
            unsigned e0 = g_csr[i];
            float2 v0 = __half22float2(hb[(size_t)unpack_src(e0) * 32 + lane]);
            float nm = unpack_dinv(e0) * dv;
            acc.x = fmaf(nm, v0.x, acc.x);
            acc.y = fmaf(nm, v0.y, acc.y);
        }
        acc.x = fmaxf(acc.x + bb.x, 0.f);   // bias + relu (layers 1,2 both relu)
        acc.y = fmaxf(acc.y + bb.y, 0.f);
        *(__half2*)&As[lr * LDA + 2 * lane] = __floats2half2_rn(acc.x, acc.y);
    }
    __syncthreads();

    // mma phase: warps 0-3 compute the 64 x FOUT tile
    if (warp < 4) {
        float acc[NT][4];
#pragma unroll
        for (int t = 0; t < NT; t++) {
            acc[t][0] = 0.f; acc[t][1] = 0.f; acc[t][2] = 0.f; acc[t][3] = 0.f;
        }
#pragma unroll
        for (int kk = 0; kk < 4; kk++) {
            unsigned a0, a1, a2, a3;
            {
                int arow = warp * 16 + (lane & 15);
                int acol = kk * 16 + (lane >> 4) * 8;
                unsigned aaddr = (unsigned)__cvta_generic_to_shared(&As[arow * LDA + acol]);
                asm volatile("ldmatrix.sync.aligned.m8n8.x4.shared.b16 {%0,%1,%2,%3}, [%4];"
                             : "=r"(a0), "=r"(a1), "=r"(a2), "=r"(a3) : "r"(aaddr));
            }
#pragma unroll
            for (int nt = 0; nt < NT; nt++) {
                unsigned b0, b1;
                int brow = kk * 16 + (lane & 15);
                unsigned baddr = (unsigned)__cvta_generic_to_shared(&Bs[brow * LDA + nt * 8]);
                asm volatile("ldmatrix.sync.aligned.m8n8.x2.trans.shared.b16 {%0,%1}, [%2];"
                             : "=r"(b0), "=r"(b1) : "r"(baddr));
                asm volatile("mma.sync.aligned.m16n8k16.row.col.f32.f16.f16.f32 "
                             "{%0,%1,%2,%3}, {%4,%5,%6,%7}, {%8,%9}, {%0,%1,%2,%3};"
                             : "+f"(acc[nt][0]), "+f"(acc[nt][1]),
                               "+f"(acc[nt][2]), "+f"(acc[nt][3])
                             : "r"(a0), "r"(a1), "r"(a2), "r"(a3), "r"(b0), "r"(b1));
            }
        }
        int r0    = node0 + warp * 16 + (lane >> 2);
        int cbase = (lane & 3) * 2;
#pragma unroll
        for (int nt = 0; nt < NT; nt++) {
            if (r0 < n)
                *(__half2*)&H[(size_t)r0 * FOUT + nt * 8 + cbase] =
                    __floats2half2_rn(acc[nt][0], acc[nt][1]);
            if (r0 + 8 < n)
                *(__half2*)&H[(size_t)(r0 + 8) * FOUT + nt * 8 + cbase] =
                    __floats2half2_rn(acc[nt][2], acc[nt][3]);
        }
    }
}

// ---------------- final aggregation (layer 3, F=32, no relu, fp32 out) ------
__global__ void __launch_bounds__(256) agg_final_kernel(const __half* __restrict__ h,
                                                        const float* __restrict__ bias,
                                                        float* __restrict__ out) {
    int node = (blockIdx.x * 256 + threadIdx.x) >> 5;
    int lane = threadIdx.x & 31;
    if (node >= N_NODES) return;

    float dv  = g_dinv[node];
    float s2  = dv * dv;
    int   beg = g_off[node];
    int   end = g_cur[node];

    float acc = __half2float(h[(size_t)node * 32 + lane]) * s2;
    int i = beg;
    for (; i + 8 <= end; i += 8) {
        unsigned e[8];
#pragma unroll
        for (int j = 0; j < 8; j++) e[j] = g_csr[i + j];
        float v[8];
#pragma unroll
        for (int j = 0; j < 8; j++)
            v[j] = __half2float(h[(size_t)unpack_src(e[j]) * 32 + lane]);
#pragma unroll
        for (int j = 0; j < 8; j++)
            acc = fmaf(unpack_dinv(e[j]) * dv, v[j], acc);
    }
    for (; i < end; i++) {
        unsigned e0 = g_csr[i];
        acc = fmaf(unpack_dinv(e0) * dv,
                   __half2float(h[(size_t)unpack_src(e0) * 32 + lane]), acc);
    }
    acc += bias[lane];
    out[(size_t)node * 32 + lane] = acc;
}

// ---------------- host-side launcher ---------------------------------------
extern "C" void kernel_launch(void* const* d_in, const int* in_sizes, int n_in,
                              void* d_out, int out_size) {
    const float* x   = (const float*)d_in[0];
    const int*   ei  = (const int*)d_in[1];     // int32 (JAX x64 disabled)
    const int*   src = ei;
    const int*   dst = ei + N_EDGES;
    const float* W1  = (const float*)d_in[2];
    const float* b1  = (const float*)d_in[3];
    const float* W2  = (const float*)d_in[4];
    const float* b2  = (const float*)d_in[5];
    const float* W3  = (const float*)d_in[6];
    const float* b3  = (const float*)d_in[7];
    float* out = (float*)d_out;

    void *p_h1, *p_h2, *p_h3;
    cudaGetSymbolAddress(&p_h1, g_h1);
    cudaGetSymbolAddress(&p_h2, g_h2);
    cudaGetSymbolAddress(&p_h3, g_h3);
    __half* h1 = (__half*)p_h1;
    __half* h2 = (__half*)p_h2;
    __half* h3 = (__half*)p_h3;

    const int n  = N_NODES;
    const int TB = 256;
    const int gE8 = (N_EDGES / 8 + TB - 1) / TB;
    const int gT64  = (N_NODES + 63) / 64;
    const int gT128 = (N_NODES + 127) / 128;
    const int gAgg = (N_NODES * 32 + TB - 1) / TB;

    // --- CSR build (3 launches) ---
    deg_kernel<<<gE8, TB>>>(dst);
    scan_kernel<<<NB_SCAN, 1024>>>();
    scatter_kernel<<<gE8, TB>>>(src, dst);

    // --- layers ---
    gemm_mma_kernel<64><<<gT128, TB>>>(x, W1, h1, n);        // h1 = X @ W1
    fused_kernel<64><<<gT64, TB>>>(h1, b1, W2, h2, n);       // h2 = relu(agg h1 + b1) @ W2
    fused_kernel<32><<<gT64, TB>>>(h2, b2, W3, h3, n);       // h3 = relu(agg h2 + b2) @ W3
    agg_final_kernel<<<gAgg, TB>>>(h3, b3, out);             // out = agg h3 + b3
}

// round 15
// speedup vs baseline: 1.0787x; 1.0213x over previous
#include <cuda_runtime.h>
#include <cuda_fp16.h>

#define N_NODES 100000
#define N_EDGES 1600000
#define NB_SCAN ((N_NODES + 1023) / 1024)   // 98 scan blocks

// ---------------- scratch (static device globals; no allocation allowed) ----
// g_cnt invariant: zero at entry of every kernel_launch execution (initially
// zero-initialized; scan_kernel re-zeroes it after consuming it).
// g_total: reset by deg_kernel (runs strictly before scan_kernel each launch).
__device__ __align__(16) int      g_cnt [N_NODES];
__device__ __align__(16) int      g_off [N_NODES];
__device__ __align__(16) int      g_cur [N_NODES];
__device__            int         g_total;
__device__ __align__(16) float    g_dinv[N_NODES];
__device__ __align__(16) unsigned g_csr [N_EDGES];      // (src<<15)|fp16(dinv[src])
__device__ __align__(16) __half   g_h1  [N_NODES * 64]; // layer-1 transformed feats
__device__ __align__(16) __half   g_h2  [N_NODES * 64]; // layer-2 transformed feats
__device__ __align__(16) __half   g_h3  [N_NODES * 32]; // layer-3 transformed feats

// pack/unpack: src in [0,2^17), dinv in (0,1] so fp16 sign bit is 0 -> 15 bits
__device__ __forceinline__ unsigned pack_edge(int s, float dv_s) {
    unsigned h = (unsigned)__half_as_ushort(__float2half_rn(dv_s));  // bit15==0
    return ((unsigned)s << 15) | h;
}
__device__ __forceinline__ int unpack_src(unsigned u) { return (int)(u >> 15); }
__device__ __forceinline__ float unpack_dinv(unsigned u) {
    return __half2float(__ushort_as_half((unsigned short)(u & 0x7FFFu)));
}

// ---------------- CSR construction ------------------------------------------
// 8 edges per thread (two int4 loads); also resets g_total for this launch.
__global__ void deg_kernel(const int* __restrict__ dst) {
    if (blockIdx.x == 0 && threadIdx.x == 0) g_total = 0;
    int base = (blockIdx.x * blockDim.x + threadIdx.x) * 8;
    if (base >= N_EDGES) return;
    int4 d4a = *(const int4*)(dst + base);
    int4 d4b = *(const int4*)(dst + base + 4);
    atomicAdd(&g_cnt[d4a.x], 1);
    atomicAdd(&g_cnt[d4a.y], 1);
    atomicAdd(&g_cnt[d4a.z], 1);
    atomicAdd(&g_cnt[d4a.w], 1);
    atomicAdd(&g_cnt[d4b.x], 1);
    atomicAdd(&g_cnt[d4b.y], 1);
    atomicAdd(&g_cnt[d4b.z], 1);
    atomicAdd(&g_cnt[d4b.w], 1);
}

// single-pass CSR offsets: per-block exclusive scan + ONE atomic block-base.
// Rows need not be in node order — any disjoint contiguous allocation works.
// Also computes dinv, inits cursors, re-zeroes g_cnt (replay invariant).
__global__ void scan_kernel() {
    __shared__ int sh[1024];
    __shared__ int base_sh;
    int i = blockIdx.x * 1024 + threadIdx.x;
    int v = (i < N_NODES) ? g_cnt[i] : 0;
    if (i < N_NODES) g_dinv[i] = rsqrtf((float)v + 1.0f);  // +1 self-loop
    sh[threadIdx.x] = v;
    __syncthreads();
#pragma unroll
    for (int s = 1; s < 1024; s <<= 1) {
        int t = 0;
        if (threadIdx.x >= s) t = sh[threadIdx.x - s];
        __syncthreads();
        if (threadIdx.x >= s) sh[threadIdx.x] += t;
        __syncthreads();
    }
    if (threadIdx.x == 1023) base_sh = atomicAdd(&g_total, sh[1023]);
    __syncthreads();
    if (i < N_NODES) {
        int o = base_sh + sh[threadIdx.x] - v;   // block base + local exclusive
        g_off[i] = o;
        g_cur[i] = o;
        g_cnt[i] = 0;   // restore invariant for next replay
    }
}

// scatter edges into CSR order; 8 edges/thread; packs fp16(dinv[src]) only
__global__ void scatter_kernel(const int* __restrict__ src,
                               const int* __restrict__ dst) {
    int base = (blockIdx.x * blockDim.x + threadIdx.x) * 8;
    if (base >= N_EDGES) return;
    int4 s4a = *(const int4*)(src + base);
    int4 s4b = *(const int4*)(src + base + 4);
    int4 d4a = *(const int4*)(dst + base);
    int4 d4b = *(const int4*)(dst + base + 4);
    float a0 = g_dinv[s4a.x], a1 = g_dinv[s4a.y], a2 = g_dinv[s4a.z], a3 = g_dinv[s4a.w];
    float a4 = g_dinv[s4b.x], a5 = g_dinv[s4b.y], a6 = g_dinv[s4b.z], a7 = g_dinv[s4b.w];
    int p0 = atomicAdd(&g_cur[d4a.x], 1);
    int p1 = atomicAdd(&g_cur[d4a.y], 1);
    int p2 = atomicAdd(&g_cur[d4a.z], 1);
    int p3 = atomicAdd(&g_cur[d4a.w], 1);
    int p4 = atomicAdd(&g_cur[d4b.x], 1);
    int p5 = atomicAdd(&g_cur[d4b.y], 1);
    int p6 = atomicAdd(&g_cur[d4b.z], 1);
    int p7 = atomicAdd(&g_cur[d4b.w], 1);
    g_csr[p0] = pack_edge(s4a.x, a0);
    g_csr[p1] = pack_edge(s4a.y, a1);
    g_csr[p2] = pack_edge(s4a.z, a2);
    g_csr[p3] = pack_edge(s4a.w, a3);
    g_csr[p4] = pack_edge(s4b.x, a4);
    g_csr[p5] = pack_edge(s4b.y, a5);
    g_csr[p6] = pack_edge(s4b.z, a6);
    g_csr[p7] = pack_edge(s4b.w, a7);
}

// ---------------- tensor-core GEMM: H[n,FOUT](fp16) = X[n,64](fp32) @ W -----
// 256-row tile, 256 threads, 16 float4 staging loads per thread (MLP 16).
// 8 warps x 2 m-tiles each in the MMA phase.
template <int FOUT>
__global__ void __launch_bounds__(256) gemm_mma_kernel(const float* __restrict__ X,
                                                       const float* __restrict__ W,
                                                       __half* __restrict__ H, int n) {
    constexpr int LDA = 72;
    constexpr int NT  = FOUT / 8;
    __shared__ __half As[256 * LDA];   // 36.9 KB
    __shared__ __half Bs[64 * LDA];    //  9.2 KB  (total 46 KB < 48 KB)
    int tid  = threadIdx.x;
    int row0 = blockIdx.x * 256;

    // stage A tile (256 x 64) fp32 -> fp16, 16 float4 loads per thread
#pragma unroll
    for (int p = tid; p < 256 * 16; p += 256) {
        int r  = p >> 4;
        int c4 = p & 15;
        int gr = row0 + r;
        float4 v = (gr < n) ? ((const float4*)(X + (size_t)gr * 64))[c4]
                            : make_float4(0.f, 0.f, 0.f, 0.f);
        *(__half2*)&As[r * LDA + c4 * 4]     = __floats2half2_rn(v.x, v.y);
        *(__half2*)&As[r * LDA + c4 * 4 + 2] = __floats2half2_rn(v.z, v.w);
    }
    // stage W (64 x FOUT) fp32 -> fp16, float4 loads
    for (int p = tid; p < 64 * (FOUT / 4); p += 256) {
        int r  = p / (FOUT / 4);
        int c4 = p % (FOUT / 4);
        float4 v = ((const float4*)(W + (size_t)r * FOUT))[c4];
        *(__half2*)&Bs[r * LDA + c4 * 4]     = __floats2half2_rn(v.x, v.y);
        *(__half2*)&Bs[r * LDA + c4 * 4 + 2] = __floats2half2_rn(v.z, v.w);
    }
    __syncthreads();

    int warp = tid >> 5;   // 8 warps, 2 m-tiles (32 rows) each
    int lane = tid & 31;
#pragma unroll
    for (int mt = 0; mt < 2; mt++) {
        int mrow = (warp * 2 + mt) * 16;
        float acc[NT][4];
#pragma unroll
        for (int t = 0; t < NT; t++) {
            acc[t][0] = 0.f; acc[t][1] = 0.f; acc[t][2] = 0.f; acc[t][3] = 0.f;
        }
#pragma unroll
        for (int kk = 0; kk < 4; kk++) {
            unsigned a0, a1, a2, a3;
            {
                int arow = mrow + (lane & 15);
                int acol = kk * 16 + (lane >> 4) * 8;
                unsigned aaddr = (unsigned)__cvta_generic_to_shared(&As[arow * LDA + acol]);
                asm volatile("ldmatrix.sync.aligned.m8n8.x4.shared.b16 {%0,%1,%2,%3}, [%4];"
                             : "=r"(a0), "=r"(a1), "=r"(a2), "=r"(a3) : "r"(aaddr));
            }
#pragma unroll
            for (int nt = 0; nt < NT; nt++) {
                unsigned b0, b1;
                int brow = kk * 16 + (lane & 15);
                unsigned baddr = (unsigned)__cvta_generic_to_shared(&Bs[brow * LDA + nt * 8]);
                asm volatile("ldmatrix.sync.aligned.m8n8.x2.trans.shared.b16 {%0,%1}, [%2];"
                             : "=r"(b0), "=r"(b1) : "r"(baddr));
                asm volatile("mma.sync.aligned.m16n8k16.row.col.f32.f16.f16.f32 "
                             "{%0,%1,%2,%3}, {%4,%5,%6,%7}, {%8,%9}, {%0,%1,%2,%3};"
                             : "+f"(acc[nt][0]), "+f"(acc[nt][1]),
                               "+f"(acc[nt][2]), "+f"(acc[nt][3])
                             : "r"(a0), "r"(a1), "r"(a2), "r"(a3), "r"(b0), "r"(b1));
            }
        }
        int r0    = row0 + mrow + (lane >> 2);
        int cbase = (lane & 3) * 2;
#pragma unroll
        for (int nt = 0; nt < NT; nt++) {
            if (r0 < n)
                *(__half2*)&H[(size_t)r0 * FOUT + nt * 8 + cbase] =
                    __floats2half2_rn(acc[nt][0], acc[nt][1]);
            if (r0 + 8 < n)
                *(__half2*)&H[(size_t)(r0 + 8) * FOUT + nt * 8 + cbase] =
                    __floats2half2_rn(acc[nt][2], acc[nt][3]);
        }
    }
}

// ---------------- fused agg(layer l) + GEMM(layer l+1) ----------------------
// 256 threads: 8 warps x 8 nodes in agg phase; ALL 8 warps in mma phase
// (warp w: m-tile w>>1, n-half w&1).
template <int FOUT>
__global__ void __launch_bounds__(256) fused_kernel(const __half* __restrict__ h_in,
                                                    const float* __restrict__ bias,
                                                    const float* __restrict__ W,
                                                    __half* __restrict__ H, int n) {
    constexpr int LDA = 72;
    constexpr int NT  = FOUT / 8;
    constexpr int NT2 = NT / 2;       // n-tiles per warp (half of FOUT)
    __shared__ __half As[64 * LDA];
    __shared__ __half Bs[64 * LDA];
    int tid   = threadIdx.x;
    int warp  = tid >> 5;
    int lane  = tid & 31;
    int node0 = blockIdx.x * 64;

    // stage W (64 x FOUT) fp32 -> fp16
    for (int p = tid; p < 64 * (FOUT / 2); p += 256) {
        int r  = p / (FOUT / 2);
        int cp = p % (FOUT / 2);
        float2 v = ((const float2*)(W + (size_t)r * FOUT))[cp];
        *(__half2*)&Bs[r * LDA + 2 * cp] = __floats2half2_rn(v.x, v.y);
    }

    // agg phase: warp w handles local rows w*8 .. w*8+7
    const half2* hb = (const half2*)h_in;
    float2 bb = ((const float2*)bias)[lane];
    for (int k = 0; k < 8; k++) {
        int lr   = warp * 8 + k;
        int node = node0 + lr;
        if (node >= n) break;
        float dv  = g_dinv[node];
        float s2  = dv * dv;
        int   beg = g_off[node];
        int   end = g_cur[node];
        float2 self = __half22float2(hb[(size_t)node * 32 + lane]);
        float2 acc;
        acc.x = self.x * s2;
        acc.y = self.y * s2;
        int i = beg;
        for (; i + 8 <= end; i += 8) {
            unsigned e[8];
#pragma unroll
            for (int j = 0; j < 8; j++) e[j] = g_csr[i + j];
            float2 v[8];
#pragma unroll
            for (int j = 0; j < 8; j++)
                v[j] = __half22float2(hb[(size_t)unpack_src(e[j]) * 32 + lane]);
#pragma unroll
            for (int j = 0; j < 8; j++) {
                float nm = unpack_dinv(e[j]) * dv;
                acc.x = fmaf(nm, v[j].x, acc.x);
                acc.y = fmaf(nm, v[j].y, acc.y);
            }
        }
        for (; i < end; i++) {
            unsigned e0 = g_csr[i];
            float2 v0 = __half22float2(hb[(size_t)unpack_src(e0) * 32 + lane]);
            float nm = unpack_dinv(e0) * dv;
            acc.x = fmaf(nm, v0.x, acc.x);
            acc.y = fmaf(nm, v0.y, acc.y);
        }
        acc.x = fmaxf(acc.x + bb.x, 0.f);   // bias + relu (layers 1,2 both relu)
        acc.y = fmaxf(acc.y + bb.y, 0.f);
        *(__half2*)&As[lr * LDA + 2 * lane] = __floats2half2_rn(acc.x, acc.y);
    }
    __syncthreads();

    // mma phase: all 8 warps; warp w -> m-tile (w>>1), n-half (w&1)
    {
        int mrow  = (warp >> 1) * 16;
        int nhalf = (warp & 1) * NT2;
        float acc[NT2][4];
#pragma unroll
        for (int t = 0; t < NT2; t++) {
            acc[t][0] = 0.f; acc[t][1] = 0.f; acc[t][2] = 0.f; acc[t][3] = 0.f;
        }
#pragma unroll
        for (int kk = 0; kk < 4; kk++) {
            unsigned a0, a1, a2, a3;
            {
                int arow = mrow + (lane & 15);
                int acol = kk * 16 + (lane >> 4) * 8;
                unsigned aaddr = (unsigned)__cvta_generic_to_shared(&As[arow * LDA + acol]);
                asm volatile("ldmatrix.sync.aligned.m8n8.x4.shared.b16 {%0,%1,%2,%3}, [%4];"
                             : "=r"(a0), "=r"(a1), "=r"(a2), "=r"(a3) : "r"(aaddr));
            }
#pragma unroll
            for (int t = 0; t < NT2; t++) {
                int nt = nhalf + t;
                unsigned b0, b1;
                int brow = kk * 16 + (lane & 15);
                unsigned baddr = (unsigned)__cvta_generic_to_shared(&Bs[brow * LDA + nt * 8]);
                asm volatile("ldmatrix.sync.aligned.m8n8.x2.trans.shared.b16 {%0,%1}, [%2];"
                             : "=r"(b0), "=r"(b1) : "r"(baddr));
                asm volatile("mma.sync.aligned.m16n8k16.row.col.f32.f16.f16.f32 "
                             "{%0,%1,%2,%3}, {%4,%5,%6,%7}, {%8,%9}, {%0,%1,%2,%3};"
                             : "+f"(acc[t][0]), "+f"(acc[t][1]),
                               "+f"(acc[t][2]), "+f"(acc[t][3])
                             : "r"(a0), "r"(a1), "r"(a2), "r"(a3), "r"(b0), "r"(b1));
            }
        }
        int r0    = node0 + mrow + (lane >> 2);
        int cbase = (lane & 3) * 2;
#pragma unroll
        for (int t = 0; t < NT2; t++) {
            int nt = nhalf + t;
            if (r0 < n)
                *(__half2*)&H[(size_t)r0 * FOUT + nt * 8 + cbase] =
                    __floats2half2_rn(acc[t][0], acc[t][1]);
            if (r0 + 8 < n)
                *(__half2*)&H[(size_t)(r0 + 8) * FOUT + nt * 8 + cbase] =
                    __floats2half2_rn(acc[t][2], acc[t][3]);
        }
    }
}

// ---------------- final aggregation (layer 3, F=32, no relu, fp32 out) ------
__global__ void __launch_bounds__(256) agg_final_kernel(const __half* __restrict__ h,
                                                        const float* __restrict__ bias,
                                                        float* __restrict__ out) {
    int node = (blockIdx.x * 256 + threadIdx.x) >> 5;
    int lane = threadIdx.x & 31;
    if (node >= N_NODES) return;

    float dv  = g_dinv[node];
    float s2  = dv * dv;
    int   beg = g_off[node];
    int   end = g_cur[node];

    float acc = __half2float(h[(size_t)node * 32 + lane]) * s2;
    int i = beg;
    for (; i + 8 <= end; i += 8) {
        unsigned e[8];
#pragma unroll
        for (int j = 0; j < 8; j++) e[j] = g_csr[i + j];
        float v[8];
#pragma unroll
        for (int j = 0; j < 8; j++)
            v[j] = __half2float(h[(size_t)unpack_src(e[j]) * 32 + lane]);
#pragma unroll
        for (int j = 0; j < 8; j++)
            acc = fmaf(unpack_dinv(e[j]) * dv, v[j], acc);
    }
    for (; i < end; i++) {
        unsigned e0 = g_csr[i];
        acc = fmaf(unpack_dinv(e0) * dv,
                   __half2float(h[(size_t)unpack_src(e0) * 32 + lane]), acc);
    }
    acc += bias[lane];
    out[(size_t)node * 32 + lane] = acc;
}

// ---------------- host-side launcher ---------------------------------------
extern "C" void kernel_launch(void* const* d_in, const int* in_sizes, int n_in,
                              void* d_out, int out_size) {
    const float* x   = (const float*)d_in[0];
    const int*   ei  = (const int*)d_in[1];     // int32 (JAX x64 disabled)
    const int*   src = ei;
    const int*   dst = ei + N_EDGES;
    const float* W1  = (const float*)d_in[2];
    const float* b1  = (const float*)d_in[3];
    const float* W2  = (const float*)d_in[4];
    const float* b2  = (const float*)d_in[5];
    const float* W3  = (const float*)d_in[6];
    const float* b3  = (const float*)d_in[7];
    float* out = (float*)d_out;

    void *p_h1, *p_h2, *p_h3;
    cudaGetSymbolAddress(&p_h1, g_h1);
    cudaGetSymbolAddress(&p_h2, g_h2);
    cudaGetSymbolAddress(&p_h3, g_h3);
    __half* h1 = (__half*)p_h1;
    __half* h2 = (__half*)p_h2;
    __half* h3 = (__half*)p_h3;

    const int n  = N_NODES;
    const int TB = 256;
    const int gE8 = (N_EDGES / 8 + TB - 1) / TB;
    const int gT64  = (N_NODES + 63) / 64;
    const int gT256 = (N_NODES + 255) / 256;
    const int gAgg = (N_NODES * 32 + TB - 1) / TB;

    // --- CSR build (3 launches) ---
    deg_kernel<<<gE8, TB>>>(dst);
    scan_kernel<<<NB_SCAN, 1024>>>();
    scatter_kernel<<<gE8, TB>>>(src, dst);

    // --- layers ---
    gemm_mma_kernel<64><<<gT256, TB>>>(x, W1, h1, n);        // h1 = X @ W1
    fused_kernel<64><<<gT64, TB>>>(h1, b1, W2, h2, n);       // h2 = relu(agg h1 + b1) @ W2
    fused_kernel<32><<<gT64, TB>>>(h2, b2, W3, h3, n);       // h3 = relu(agg h2 + b2) @ W3
    agg_final_kernel<<<gAgg, TB>>>(h3, b3, out);             // out = agg h3 + b3
}